// round 14
// baseline (speedup 1.0000x reference)
#include <cuda_runtime.h>
#include <cuda_bf16.h>
#include <cuda_fp16.h>
#include <cstdint>

#define NN    50000
#define MPAD  50048              // 391 * 128
#define KCH   256
#define HEADS 8
#define OUTC  32
#define NE    800000

#define K1_TILES 782             // 2 x 391
#define HIST_BLOCKS 3125         // 800000 / 256
#define SCAT_BLOCKS 782          // ceil(800000 / 1024)

// ---------------- scratch (static __device__, no allocation) ----------------
__device__ __half   g_xph[(size_t)NN * KCH];    // projected features, fp16
__device__ float    g_al[NN * HEADS];
__device__ float    g_ar[NN * HEADS];
__device__ int      g_deg[NN];
__device__ int      g_rowptr[NN + 1];
__device__ int      g_cursor[NN];
__device__ int      g_csrsrc[NE];
__device__ uint32_t g_whi[KCH * (KCH / 2)];     // W hi, packed bf16x2 [n][k/2]
__device__ uint32_t g_wlo[KCH * (KCH / 2)];     // W lo (residual)

// ---------------- helpers ----------------
__device__ __forceinline__ uint32_t pack_bf2(float a, float b) {
    __nv_bfloat162 t = __halves2bfloat162(__float2bfloat16(a), __float2bfloat16(b));
    return *reinterpret_cast<uint32_t*>(&t);
}
__device__ __forceinline__ uint32_t pack_h2(float a, float b) {
    __half2 t = __floats2half2_rn(a, b);
    return *reinterpret_cast<uint32_t*>(&t);
}
__device__ __forceinline__ void mma_bf16(float* c, const uint32_t* a,
                                         uint32_t b0, uint32_t b1) {
    asm volatile(
        "mma.sync.aligned.m16n8k16.row.col.f32.bf16.bf16.f32 "
        "{%0,%1,%2,%3}, {%4,%5,%6,%7}, {%8,%9}, {%0,%1,%2,%3};"
        : "+f"(c[0]), "+f"(c[1]), "+f"(c[2]), "+f"(c[3])
        : "r"(a[0]), "r"(a[1]), "r"(a[2]), "r"(a[3]), "r"(b0), "r"(b1));
}
__device__ __forceinline__ void ldsm_x4(uint32_t* r, uint32_t addr) {
    asm volatile(
        "ldmatrix.sync.aligned.m8n8.x4.shared.b16 {%0,%1,%2,%3}, [%4];"
        : "=r"(r[0]), "=r"(r[1]), "=r"(r[2]), "=r"(r[3]) : "r"(addr));
}
__device__ __forceinline__ int ld_idx(const void* ei, int pos, int is64) {
    if (is64) return (int)((const long long*)ei)[pos];
    return ((const int*)ei)[pos];
}
__device__ __forceinline__ void fma8(float* acc, float w, uint4 u) {
    float2 f0 = __half22float2(*(__half2*)&u.x);
    float2 f1 = __half22float2(*(__half2*)&u.y);
    float2 f2 = __half22float2(*(__half2*)&u.z);
    float2 f3 = __half22float2(*(__half2*)&u.w);
    acc[0] += w * f0.x; acc[1] += w * f0.y;
    acc[2] += w * f1.x; acc[3] += w * f1.y;
    acc[4] += w * f2.x; acc[5] += w * f2.y;
    acc[6] += w * f3.x; acc[7] += w * f3.y;
}
__device__ __forceinline__ float expleaky(float lg) {
    float a = lg > 0.f ? lg : 0.2f * lg;
    return __expf(a);
}

// ---------------- kzW: W split (main stream, gates f1) --------------------
__global__ void kzW(const float* __restrict__ W) {
    int i = blockIdx.x * 256 + threadIdx.x;          // n*128 + kk
    int n = i >> 7, kk = i & 127;
    float2 v = *(const float2*)(W + (size_t)n * KCH + kk * 2);
    float hx = __bfloat162float(__float2bfloat16(v.x));
    float hy = __bfloat162float(__float2bfloat16(v.y));
    g_whi[i] = pack_bf2(v.x, v.y);
    g_wlo[i] = pack_bf2(v.x - hx, v.y - hy);
}

// ---------------- kzD: zero degree counters (side stream) -----------------
__global__ void kzD() {
    int i = blockIdx.x * 256 + threadIdx.x;
    if (i < NN) g_deg[i] = 0;
}

// ---------------- kh: dst-degree histogram (side stream) -------------------
__global__ void kh_hist(const void* __restrict__ ei) {
    __shared__ int s_is64;
    int tid = threadIdx.x;
    if (tid == 0) s_is64 = 1;
    __syncthreads();
    if (tid < 64) {
        long long v = ((const long long*)ei)[tid];
        if (v < 0 || v >= NN) s_is64 = 0;   // benign race: all writes = 0
    }
    __syncthreads();
    int is64 = s_is64;
    int e = blockIdx.x * 256 + tid;
    if (e < NE) atomicAdd(&g_deg[ld_idx(ei, NE + e, is64)], 1);
}

// ---------------- F1: GEMM xp = x @ W^T, ldmatrix fragments ----------------
__global__ __launch_bounds__(256, 2) void f1(const float* __restrict__ x,
                                             const float* __restrict__ attn_l,
                                             const float* __restrict__ attn_r) {
    __shared__ uint32_t sW[2][128][20];   // [hi/lo][n][k-u32], cols 0..15 used
    __shared__ uint32_t sA[2][128][20];   // [hi/lo][m][k-u32]
    __shared__ float    s_attn[2][128];

    int tid = threadIdx.x;
    int lane = tid & 31, wid = tid >> 5;
    int bx = blockIdx.x & 1, by = blockIdx.x >> 1;
    int m0 = by * 128;
    int n0 = bx * 128;
    int qr = lane >> 2;        // groupID
    int qc = lane & 3;         // thread-in-group
    int wm = wid & 3;          // M stripe (32 rows)
    int wn = wid >> 2;         // N stripe (64 cols)

    if (tid < 128) s_attn[0][tid] = attn_l[n0 + tid];
    else           s_attn[1][tid - 128] = attn_r[n0 + tid - 128];

    float acc[2][8][4];        // [m-tile][n-tile][frag]
#pragma unroll
    for (int mt = 0; mt < 2; mt++)
#pragma unroll
        for (int nt = 0; nt < 8; nt++)
#pragma unroll
            for (int j = 0; j < 4; j++) acc[mt][nt][j] = 0.f;

    int rl0 = wm * 32 + qr;
    int nb  = wn * 64;

    // ---- ldmatrix base addresses (bytes, shared space) ----
    // A x4 groups: (m-lo,k-lo)(m-hi,k-lo)(m-lo,k-hi)(m-hi,k-hi) -> a0..a3
    uint32_t aBase[2][2];      // [arr][mt]
    {
        int ar = wm * 32 + (lane & 15);      // row within tile for this lane
        int ak = (lane >> 4) * 4;            // k-half column (0 or 4 u32)
#pragma unroll
        for (int arr = 0; arr < 2; arr++)
#pragma unroll
            for (int mt = 0; mt < 2; mt++)
                aBase[arr][mt] = (uint32_t)__cvta_generic_to_shared(
                    &sA[arr][ar + mt * 16][ak]);
    }
    // W x4 groups: (nt,k-lo)(nt,k-hi)(nt+1,k-lo)(nt+1,k-hi) -> b0(nt),b1(nt),b0(nt+1),b1(nt+1)
    uint32_t wBase[2][4];      // [arr][pair]
    {
        int wr = lane & 7;
        int wg = lane >> 3;                  // 0..3
#pragma unroll
        for (int arr = 0; arr < 2; arr++)
#pragma unroll
            for (int p = 0; p < 4; p++) {
                int row = nb + (2 * p + (wg >> 1)) * 8 + wr;
                int col = (wg & 1) * 4;
                wBase[arr][p] = (uint32_t)__cvta_generic_to_shared(
                    &sW[arr][row][col]);
            }
    }

    // staging coordinates for this thread (4 items/chunk)
    int st_row = tid >> 3;               // rows tid>>3, +32, +64, +96
    int st_f4  = tid & 7;

    // ---- prologue: prefetch A chunk 0 into registers ----
    float4 pre[4];
#pragma unroll
    for (int j = 0; j < 4; j++) {
        int row = st_row + j * 32;
        int grow = m0 + row;
        pre[j] = (grow < NN)
                 ? *(const float4*)(x + (size_t)grow * KCH + 0 * 32 + st_f4 * 4)
                 : make_float4(0.f, 0.f, 0.f, 0.f);
    }

    for (int ch = 0; ch < 8; ch++) {      // K chunks of 32 (16 u32)
        // ---- W chunk via cp.async ----
#pragma unroll
        for (int i = tid; i < 1024; i += 256) {
            int arr = i >> 9;
            int row = (i >> 2) & 127;
            int c4  = i & 3;
            const uint32_t* src = (arr ? g_wlo : g_whi)
                                  + (size_t)(n0 + row) * 128 + ch * 16 + c4 * 4;
            uint32_t daddr = (uint32_t)__cvta_generic_to_shared(&sW[arr][row][c4 * 4]);
            asm volatile("cp.async.ca.shared.global [%0], [%1], 16;"
                         :: "r"(daddr), "l"(src));
        }
        asm volatile("cp.async.commit_group;");

        // ---- convert prefetched A (chunk ch) -> split smem ----
#pragma unroll
        for (int j = 0; j < 4; j++) {
            int row = st_row + j * 32;
            float4 v = pre[j];
            float hx = __bfloat162float(__float2bfloat16(v.x));
            float hy = __bfloat162float(__float2bfloat16(v.y));
            float hz = __bfloat162float(__float2bfloat16(v.z));
            float hw = __bfloat162float(__float2bfloat16(v.w));
            *(uint2*)&sA[0][row][st_f4 * 2] =
                make_uint2(pack_bf2(v.x, v.y), pack_bf2(v.z, v.w));
            *(uint2*)&sA[1][row][st_f4 * 2] =
                make_uint2(pack_bf2(v.x - hx, v.y - hy), pack_bf2(v.z - hz, v.w - hw));
        }

        // ---- prefetch A (chunk ch+1) ----
        if (ch < 7) {
#pragma unroll
            for (int j = 0; j < 4; j++) {
                int row = st_row + j * 32;
                int grow = m0 + row;
                pre[j] = (grow < NN)
                         ? *(const float4*)(x + (size_t)grow * KCH + (ch + 1) * 32 + st_f4 * 4)
                         : make_float4(0.f, 0.f, 0.f, 0.f);
            }
        }

        asm volatile("cp.async.wait_group 0;" ::: "memory");
        __syncthreads();

#pragma unroll
        for (int kc = 0; kc < 2; kc++) {          // 2 x k16 per chunk
            uint32_t klb = kc * 32;               // byte offset of this k16
            uint32_t ahi[2][4], alo[2][4];
            ldsm_x4(ahi[0], aBase[0][0] + klb);
            ldsm_x4(ahi[1], aBase[0][1] + klb);
            ldsm_x4(alo[0], aBase[1][0] + klb);
            ldsm_x4(alo[1], aBase[1][1] + klb);
#pragma unroll
            for (int p = 0; p < 4; p++) {
                uint32_t bh[4], bl[4];
                ldsm_x4(bh, wBase[0][p] + klb);
                ldsm_x4(bl, wBase[1][p] + klb);
                int nt0 = 2 * p, nt1 = 2 * p + 1;
#pragma unroll
                for (int mt = 0; mt < 2; mt++) {
                    mma_bf16(acc[mt][nt0], ahi[mt], bh[0], bh[1]);
                    mma_bf16(acc[mt][nt0], ahi[mt], bl[0], bl[1]);
                    mma_bf16(acc[mt][nt0], alo[mt], bh[0], bh[1]);
                    mma_bf16(acc[mt][nt1], ahi[mt], bh[2], bh[3]);
                    mma_bf16(acc[mt][nt1], ahi[mt], bl[2], bl[3]);
                    mma_bf16(acc[mt][nt1], alo[mt], bh[2], bh[3]);
                }
            }
        }
        __syncthreads();
    }

    // ---- epilogue: write xp as fp16 ----
#pragma unroll
    for (int mt = 0; mt < 2; mt++) {
        int row0 = m0 + rl0 + mt * 16;
        int row1 = row0 + 8;
        bool v0 = row0 < NN, v1 = row1 < NN;
#pragma unroll
        for (int nt = 0; nt < 8; nt++) {
            int col = n0 + nb + nt * 8 + qc * 2;
            if (v0) *(uint32_t*)(g_xph + (size_t)row0 * KCH + col) =
                        pack_h2(acc[mt][nt][0], acc[mt][nt][1]);
            if (v1) *(uint32_t*)(g_xph + (size_t)row1 * KCH + col) =
                        pack_h2(acc[mt][nt][2], acc[mt][nt][3]);
        }
    }

    // ---- fused al/ar (fp32, from registers) ----
#pragma unroll
    for (int hl = 0; hl < 2; hl++) {
#pragma unroll
        for (int mt = 0; mt < 2; mt++) {
            float sl0 = 0.f, sr0 = 0.f, sl1 = 0.f, sr1 = 0.f;
#pragma unroll
            for (int t = 0; t < 4; t++) {
                int nt = hl * 4 + t;
                int c = nb + nt * 8 + qc * 2;
                float L0 = s_attn[0][c], L1 = s_attn[0][c + 1];
                float R0 = s_attn[1][c], R1 = s_attn[1][c + 1];
                sl0 += acc[mt][nt][0] * L0 + acc[mt][nt][1] * L1;
                sr0 += acc[mt][nt][0] * R0 + acc[mt][nt][1] * R1;
                sl1 += acc[mt][nt][2] * L0 + acc[mt][nt][3] * L1;
                sr1 += acc[mt][nt][2] * R0 + acc[mt][nt][3] * R1;
            }
            sl0 += __shfl_xor_sync(0xffffffffu, sl0, 1);
            sl0 += __shfl_xor_sync(0xffffffffu, sl0, 2);
            sr0 += __shfl_xor_sync(0xffffffffu, sr0, 1);
            sr0 += __shfl_xor_sync(0xffffffffu, sr0, 2);
            sl1 += __shfl_xor_sync(0xffffffffu, sl1, 1);
            sl1 += __shfl_xor_sync(0xffffffffu, sl1, 2);
            sr1 += __shfl_xor_sync(0xffffffffu, sr1, 1);
            sr1 += __shfl_xor_sync(0xffffffffu, sr1, 2);
            if (qc == 0) {
                int head = bx * 4 + wn * 2 + hl;
                int row0 = m0 + rl0 + mt * 16;
                int row1 = row0 + 8;
                if (row0 < NN) { g_al[row0 * HEADS + head] = sl0;
                                 g_ar[row0 * HEADS + head] = sr0; }
                if (row1 < NN) { g_al[row1 * HEADS + head] = sl1;
                                 g_ar[row1 * HEADS + head] = sr1; }
            }
        }
    }
}

// ---------------- k4: single-block exclusive scan -> rowptr/cursor -------
__global__ void k4_scan() {
    __shared__ int swarp[32];
    __shared__ int stot;
    int tid = threadIdx.x, lane = tid & 31, wid = tid >> 5;
    int carry = 0;
    for (int base = 0; base < NN; base += 1024) {
        int i = base + tid;
        int v = (i < NN) ? g_deg[i] : 0;
        int incl = v;
#pragma unroll
        for (int d = 1; d < 32; d <<= 1) {
            int t = __shfl_up_sync(0xffffffffu, incl, d);
            if (lane >= d) incl += t;
        }
        if (lane == 31) swarp[wid] = incl;
        __syncthreads();
        if (wid == 0) {
            int wv = swarp[lane];
            int wi = wv;
#pragma unroll
            for (int d = 1; d < 32; d <<= 1) {
                int t = __shfl_up_sync(0xffffffffu, wi, d);
                if (lane >= d) wi += t;
            }
            if (lane == 31) stot = wi;
            swarp[lane] = wi - wv;
        }
        __syncthreads();
        int excl = carry + swarp[wid] + incl - v;
        if (i < NN) { g_rowptr[i] = excl; g_cursor[i] = excl; }
        carry += stot;
        __syncthreads();
    }
    if (tid == 0) g_rowptr[NN] = carry;
}

// ---------------- k5: scatter edges into CSR buckets ----------------
__global__ void k5_scatter(const void* __restrict__ ei) {
    __shared__ int s_is64;
    int tid = threadIdx.x;
    if (tid == 0) s_is64 = 1;
    __syncthreads();
    if (tid < 64) {
        long long v = ((const long long*)ei)[tid];
        if (v < 0 || v >= NN) s_is64 = 0;
    }
    __syncthreads();
    int is64 = s_is64;
    int base = blockIdx.x * 1024 + tid;

    int s[4], d[4];
    bool val[4];
#pragma unroll
    for (int j = 0; j < 4; j++) {
        int e = base + j * 256;
        val[j] = e < NE;
        if (val[j]) {
            s[j] = ld_idx(ei, e, is64);
            d[j] = ld_idx(ei, NE + e, is64);
        }
    }
#pragma unroll
    for (int j = 0; j < 4; j++) {
        if (val[j]) {
            int pos = atomicAdd(&g_cursor[d[j]], 1);
            g_csrsrc[pos] = s[j];
        }
    }
}

// ---------------- k6: fused softmax + aggregate, 4 chains ----------------
__global__ __launch_bounds__(256) void k6_gather(float* __restrict__ out) {
    int node = blockIdx.x * 8 + (threadIdx.x >> 5);
    if (node >= NN) return;
    int lane = threadIdx.x & 31;
    int c0 = lane * 8;
    int h  = lane >> 2;

    float arn = g_ar[node * HEADS + h];

    float ca[8] = {0,0,0,0,0,0,0,0};
    float cb[8] = {0,0,0,0,0,0,0,0};
    float cc[8] = {0,0,0,0,0,0,0,0};
    float cd[8] = {0,0,0,0,0,0,0,0};
    float wa, wb = 0.f, wc = 0.f, wd = 0.f;

    // seed chain a with the self loop
    {
        float w = expleaky(g_al[node * HEADS + h] + arn);
        wa = w;
        uint4 u = *(const uint4*)(g_xph + (size_t)node * KCH + c0);
        fma8(ca, w, u);
    }

    int p   = g_rowptr[node];
    int end = g_rowptr[node + 1];

    for (; p + 4 <= end; p += 4) {
        int s0 = g_csrsrc[p];
        int s1 = g_csrsrc[p + 1];
        int s2 = g_csrsrc[p + 2];
        int s3 = g_csrsrc[p + 3];
        float l0 = g_al[s0 * HEADS + h];
        float l1 = g_al[s1 * HEADS + h];
        float l2 = g_al[s2 * HEADS + h];
        float l3 = g_al[s3 * HEADS + h];
        uint4 u0 = *(const uint4*)(g_xph + (size_t)s0 * KCH + c0);
        uint4 u1 = *(const uint4*)(g_xph + (size_t)s1 * KCH + c0);
        uint4 u2 = *(const uint4*)(g_xph + (size_t)s2 * KCH + c0);
        uint4 u3 = *(const uint4*)(g_xph + (size_t)s3 * KCH + c0);
        float w0 = expleaky(l0 + arn);
        float w1 = expleaky(l1 + arn);
        float w2 = expleaky(l2 + arn);
        float w3 = expleaky(l3 + arn);
        wa += w0; wb += w1; wc += w2; wd += w3;
        fma8(ca, w0, u0);
        fma8(cb, w1, u1);
        fma8(cc, w2, u2);
        fma8(cd, w3, u3);
    }
    for (; p < end; p++) {
        int s0 = g_csrsrc[p];
        float w = expleaky(g_al[s0 * HEADS + h] + arn);
        wa += w;
        uint4 u = *(const uint4*)(g_xph + (size_t)s0 * KCH + c0);
        fma8(ca, w, u);
    }

    float inv = 1.f / fmaxf(wa + wb + wc + wd, 1e-6f);
    float* op = out + (size_t)node * KCH + c0;
    *(float4*)(op)     = make_float4((ca[0]+cb[0]+cc[0]+cd[0]) * inv,
                                     (ca[1]+cb[1]+cc[1]+cd[1]) * inv,
                                     (ca[2]+cb[2]+cc[2]+cd[2]) * inv,
                                     (ca[3]+cb[3]+cc[3]+cd[3]) * inv);
    *(float4*)(op + 4) = make_float4((ca[4]+cb[4]+cc[4]+cd[4]) * inv,
                                     (ca[5]+cb[5]+cc[5]+cd[5]) * inv,
                                     (ca[6]+cb[6]+cc[6]+cd[6]) * inv,
                                     (ca[7]+cb[7]+cc[7]+cd[7]) * inv);
}

// ---------------- launch: fork CSR chain onto a side stream ---------------
extern "C" void kernel_launch(void* const* d_in, const int* in_sizes, int n_in,
                              void* d_out, int out_size) {
    const float* x      = (const float*)d_in[0];
    const void*  ei     = d_in[1];
    const float* W      = (const float*)d_in[2];
    const float* attn_l = (const float*)d_in[3];
    const float* attn_r = (const float*)d_in[4];
    float*       out    = (float*)d_out;

    cudaStream_t s2;
    cudaEvent_t evFork, evJoin;
    cudaStreamCreateWithFlags(&s2, cudaStreamNonBlocking);
    cudaEventCreateWithFlags(&evFork, cudaEventDisableTiming);
    cudaEventCreateWithFlags(&evJoin, cudaEventDisableTiming);

    cudaEventRecord(evFork, 0);
    cudaStreamWaitEvent(s2, evFork, 0);

    // side branch: CSR build (independent of the GEMM)
    kzD<<<(NN + 255) / 256, 256, 0, s2>>>();
    kh_hist<<<HIST_BLOCKS, 256, 0, s2>>>(ei);
    k4_scan<<<1, 1024, 0, s2>>>();
    k5_scatter<<<SCAT_BLOCKS, 256, 0, s2>>>(ei);
    cudaEventRecord(evJoin, s2);

    // main branch: W split + GEMM (runs concurrently with CSR build)
    kzW<<<128, 256>>>(W);
    f1<<<K1_TILES, 256>>>(x, attn_l, attn_r);

    cudaStreamWaitEvent(0, evJoin, 0);                 // join before gather
    k6_gather<<<(NN + 7) / 8, 256>>>(out);

    cudaEventDestroy(evFork);
    cudaEventDestroy(evJoin);
    cudaStreamDestroy(s2);
}